// round 6
// baseline (speedup 1.0000x reference)
#include <cuda_runtime.h>
#include <cstdint>

#define IN_C     16
#define OUT_C    16
#define POS_C    16
#define KOFF     8
#define TEMP     8.0f
#define TPB      128
#define WPB      4          // warps per block
#define TILE     32         // edges per warp-tile
#define DSTRIDE  20         // padded floats per edge in s_d

// ---------------------------------------------------------------------------
// Kernel 1: out[n, o] = bias[o]
// ---------------------------------------------------------------------------
__global__ void init_out_kernel(float* __restrict__ out,
                                const float* __restrict__ bias,
                                int total) {
    int idx = blockIdx.x * blockDim.x + threadIdx.x;
    if (idx < total) out[idx] = bias[idx & (OUT_C - 1)];
}

// packed fp32x2 FMA: y += w * xv  (sm_100+)
#define PKFMA(y, w, xv) \
    asm("fma.rn.f32x2 %0, %1, %2, %0;" : "+l"(y) : "l"(w), "l"(xv))
#define PACK2(u, a, b) \
    asm("mov.b64 %0, {%1, %2};" : "=l"(u) : "f"(a), "f"(b))

__device__ __forceinline__ float upk_sum(unsigned long long v) {
    float lo, hi;
    asm("mov.b64 {%0, %1}, %2;" : "=f"(lo), "=f"(hi) : "l"(v));
    return lo + hi;
}

// ---------------------------------------------------------------------------
// Warp-cooperative kernel, dual-tile software pipeline:
//   Gather (both tiles, 8 passes, 4 lanes/edge 16B chunks): pos diff -> s_d,
//     x -> s_x, rows -> s_r (double-buffered). All ei LDGs hoisted for MLP.
//   Per tile: softmax (lane/edge, packed f32x2 distance math, offsets
//     pre-scaled by -2), then phase B (warp/edge, persistent register
//     weights, packed FMAs, shfl k-combine, direct scalar red scatter).
// ---------------------------------------------------------------------------
__global__ __launch_bounds__(TPB, 4)
void genconv_coop_kernel(const float* __restrict__ x,
                         const float* __restrict__ pos,
                         const int*   __restrict__ ei,
                         const float* __restrict__ ea,
                         const float* __restrict__ offset,
                         const float* __restrict__ weight,
                         float* __restrict__ out,
                         int E, int nWarpsTotal) {
    __shared__ __align__(16) float s_off2[KOFF * POS_C];     // -2 * offset
    __shared__ float s_o2[KOFF];
    __shared__ __align__(16) float s_d[WPB][2][TILE * DSTRIDE]; // 5KB/warp
    __shared__ __align__(16) ulonglong2 s_x[WPB][2][TILE * 4];  // 4KB/warp
    __shared__ __align__(16) float s_al[WPB][TILE * KOFF];      // 1KB/warp
    __shared__ int   s_r [WPB][2][TILE];

    const int tid  = threadIdx.x;
    const int lane = tid & 31;
    const int wrp  = tid >> 5;
    const int o    = lane & 15;
    const int kh   = lane >> 4;          // k-half: 0 -> k0..3, 1 -> k4..7
    const int ebg  = lane >> 2;          // gather: edge-in-pass
    const int q    = lane & 3;           // gather: 16B chunk

    for (int i = tid; i < KOFF * POS_C; i += TPB) s_off2[i] = offset[i];
    __syncthreads();
    if (tid < KOFF) {
        float s = 0.f;
#pragma unroll
        for (int p = 0; p < POS_C; p++) {
            float v = s_off2[tid * POS_C + p];
            s += v * v;
        }
        s_o2[tid] = s;
    }
    __syncthreads();
    for (int i = tid; i < KOFF * POS_C; i += TPB) s_off2[i] *= -2.0f;
    __syncthreads();

    // persistent weights: W[kh*4+j][o][i], i-pairs packed in u64
    ulonglong2 wr[4][4];
#pragma unroll
    for (int j = 0; j < 4; j++) {
#pragma unroll
        for (int qq = 0; qq < 4; qq++) {
            wr[j][qq] = *reinterpret_cast<const ulonglong2*>(
                weight + ((kh * 4 + j) * (OUT_C * IN_C) + o * IN_C + qq * 4));
        }
    }

    const int gwarp  = blockIdx.x * WPB + wrp;
    const int nTiles = (E + TILE - 1) / TILE;
    const int nPairs = (nTiles + 1) / 2;

    for (int u = gwarp; u < nPairs; u += nWarpsTotal) {
        const int t0 = 2 * u;

        // ============ Gather both tiles: 8 passes ============
        int rA[8], cA[8];
#pragma unroll
        for (int pp = 0; pp < 8; pp++) {
            int tt = t0 + (pp >> 2);
            int eb = (pp & 3) * 8 + ebg;
            int e  = min(tt * TILE + eb, E - 1);
            rA[pp] = ei[e];
            cA[pp] = ei[E + e];
        }
#pragma unroll
        for (int pp = 0; pp < 8; pp++) {
            int b  = pp >> 2;
            int eb = (pp & 3) * 8 + ebg;
            float4 av = *reinterpret_cast<const float4*>(
                pos + (size_t)cA[pp] * POS_C + q * 4);
            float4 bv = *reinterpret_cast<const float4*>(
                pos + (size_t)rA[pp] * POS_C + q * 4);
            float4 dq;
            dq.x = av.x - bv.x; dq.y = av.y - bv.y;
            dq.z = av.z - bv.z; dq.w = av.w - bv.w;
            *reinterpret_cast<float4*>(&s_d[wrp][b][eb * DSTRIDE + q * 4]) = dq;
            s_x[wrp][b][eb * 4 + q] = *reinterpret_cast<const ulonglong2*>(
                x + (size_t)cA[pp] * IN_C + q * 4);
            if (q == 0) s_r[wrp][b][eb] = rA[pp];
        }
        __syncwarp();

        // ============ Process the two tiles ============
#pragma unroll 1
        for (int b = 0; b < 2; b++) {
            const int t = t0 + b;
            const float*      dw = s_d[wrp][b];
            const ulonglong2* xw = s_x[wrp][b];
            const int*        rw = s_r[wrp][b];
            float*            aw = s_al[wrp];

            // ---- softmax: lane per edge ----
            {
                int et = t * TILE + lane;
                int valid = (et < E);
                int e = min(et, E - 1);

                unsigned long long dp[8];
#pragma unroll
                for (int j = 0; j < 4; j++) {
                    float4 v = *reinterpret_cast<const float4*>(
                        dw + lane * DSTRIDE + j * 4);
                    PACK2(dp[2*j + 0], v.x, v.y);
                    PACK2(dp[2*j + 1], v.z, v.w);
                }
                unsigned long long a2 = 0ull;
#pragma unroll
                for (int j = 0; j < 8; j++) PKFMA(a2, dp[j], dp[j]);
                float d2 = upk_sum(a2);

                float logit[KOFF];
                float mx = -1e30f;
#pragma unroll
                for (int k = 0; k < KOFF; k++) {
                    const ulonglong2* op =
                        reinterpret_cast<const ulonglong2*>(s_off2 + k * POS_C);
                    unsigned long long da = 0ull;
#pragma unroll
                    for (int j = 0; j < 4; j++) {
                        ulonglong2 ov = op[j];   // broadcast LDS.128
                        PKFMA(da, dp[2*j + 0], ov.x);
                        PKFMA(da, dp[2*j + 1], ov.y);
                    }
                    float sq = fmaxf(d2 + s_o2[k] + upk_sum(da), 0.0f);
                    float l = -TEMP * sqrtf(sq);
                    logit[k] = l;
                    mx = fmaxf(mx, l);
                }
                float a[KOFF];
                float asum = 0.f;
#pragma unroll
                for (int k = 0; k < KOFF; k++) {
                    float v = __expf(logit[k] - mx);
                    a[k] = v;
                    asum += v;
                }
                float inv = valid ? (ea[e] / asum) : 0.0f;
                float4* aw4 = reinterpret_cast<float4*>(aw + lane * KOFF);
                aw4[0] = make_float4(a[0]*inv, a[1]*inv, a[2]*inv, a[3]*inv);
                aw4[1] = make_float4(a[4]*inv, a[5]*inv, a[6]*inv, a[7]*inv);
            }
            __syncwarp();

            // ---- phase B: warp per edge, direct scatter ----
#pragma unroll 2
            for (int eb = 0; eb < TILE; eb++) {
                float4 a4 = *reinterpret_cast<const float4*>(
                    aw + eb * KOFF + kh * 4);
                ulonglong2 xv0 = xw[eb * 4 + 0];
                ulonglong2 xv1 = xw[eb * 4 + 1];
                ulonglong2 xv2 = xw[eb * 4 + 2];
                ulonglong2 xv3 = xw[eb * 4 + 3];

                unsigned long long c0 = 0ull, c1 = 0ull, c2 = 0ull, c3 = 0ull;
                PKFMA(c0, wr[0][0].x, xv0.x); PKFMA(c0, wr[0][0].y, xv0.y);
                PKFMA(c1, wr[1][0].x, xv0.x); PKFMA(c1, wr[1][0].y, xv0.y);
                PKFMA(c2, wr[2][0].x, xv0.x); PKFMA(c2, wr[2][0].y, xv0.y);
                PKFMA(c3, wr[3][0].x, xv0.x); PKFMA(c3, wr[3][0].y, xv0.y);
                PKFMA(c0, wr[0][1].x, xv1.x); PKFMA(c0, wr[0][1].y, xv1.y);
                PKFMA(c1, wr[1][1].x, xv1.x); PKFMA(c1, wr[1][1].y, xv1.y);
                PKFMA(c2, wr[2][1].x, xv1.x); PKFMA(c2, wr[2][1].y, xv1.y);
                PKFMA(c3, wr[3][1].x, xv1.x); PKFMA(c3, wr[3][1].y, xv1.y);
                PKFMA(c0, wr[0][2].x, xv2.x); PKFMA(c0, wr[0][2].y, xv2.y);
                PKFMA(c1, wr[1][2].x, xv2.x); PKFMA(c1, wr[1][2].y, xv2.y);
                PKFMA(c2, wr[2][2].x, xv2.x); PKFMA(c2, wr[2][2].y, xv2.y);
                PKFMA(c3, wr[3][2].x, xv2.x); PKFMA(c3, wr[3][2].y, xv2.y);
                PKFMA(c0, wr[0][3].x, xv3.x); PKFMA(c0, wr[0][3].y, xv3.y);
                PKFMA(c1, wr[1][3].x, xv3.x); PKFMA(c1, wr[1][3].y, xv3.y);
                PKFMA(c2, wr[2][3].x, xv3.x); PKFMA(c2, wr[2][3].y, xv3.y);
                PKFMA(c3, wr[3][3].x, xv3.x); PKFMA(c3, wr[3][3].y, xv3.y);

                float part = a4.x * upk_sum(c0);
                part = fmaf(a4.y, upk_sum(c1), part);
                part = fmaf(a4.z, upk_sum(c2), part);
                part = fmaf(a4.w, upk_sum(c3), part);
                part += __shfl_xor_sync(0xffffffffu, part, 16);

                int rr = rw[eb];                       // broadcast LDS
                if (lane < 16) {
                    float* dst = out + (size_t)rr * OUT_C + o;
                    asm volatile("red.global.add.f32 [%0], %1;"
                                 :: "l"(dst), "f"(part) : "memory");
                }
            }
            __syncwarp();
        }
    }
}

// ---------------------------------------------------------------------------
extern "C" void kernel_launch(void* const* d_in, const int* in_sizes, int n_in,
                              void* d_out, int out_size) {
    const float* x      = (const float*)d_in[0];
    const float* pos    = (const float*)d_in[1];
    const int*   ei     = (const int*)  d_in[2];
    const float* ea     = (const float*)d_in[3];
    const float* offset = (const float*)d_in[4];
    const float* weight = (const float*)d_in[5];
    const float* bias   = (const float*)d_in[6];
    float* out = (float*)d_out;

    int E = in_sizes[3];
    int total_out = out_size;

    int init_blocks = (total_out + 255) / 256;
    init_out_kernel<<<init_blocks, 256>>>(out, bias, total_out);

    const int blocks = 592;                 // 4 per SM on 148-SM B200
    const int nWarpsTotal = blocks * WPB;
    genconv_coop_kernel<<<blocks, TPB>>>(x, pos, ei, ea, offset, weight,
                                         out, E, nWarpsTotal);
}

// round 8
// speedup vs baseline: 1.8724x; 1.8724x over previous
#include <cuda_runtime.h>
#include <cstdint>

#define IN_C     16
#define OUT_C    16
#define POS_C    16
#define KOFF     8
#define TEMP     8.0f
#define TPB      128
#define TILE_E   128
#define DSTRIDE  20
#define ASTRIDE  48            // bytes per A/B smem row (16 bf16 data + pad)

// ---------------------------------------------------------------------------
__global__ void init_out_kernel(float* __restrict__ out,
                                const float* __restrict__ bias, int total) {
    int idx = blockIdx.x * blockDim.x + threadIdx.x;
    if (idx < total) out[idx] = bias[idx & (OUT_C - 1)];
}

// ---------------------------------------------------------------------------
__device__ __forceinline__ uint32_t smem_u32(const void* p) {
    uint32_t a;
    asm("{ .reg .u64 t; cvta.to.shared.u64 t, %1; cvt.u32.u64 %0, t; }"
        : "=r"(a) : "l"(p));
    return a;
}
// pack two floats to bf16x2: {hi half = cvt(h), lo half = cvt(l)}
__device__ __forceinline__ uint32_t bf2(float h, float l) {
    uint32_t r;
    asm("cvt.rn.bf16x2.f32 %0, %1, %2;" : "=r"(r) : "f"(h), "f"(l));
    return r;
}
__device__ __forceinline__ float bf_lo(uint32_t v) {
    return __uint_as_float(v << 16);
}
__device__ __forceinline__ float bf_hi(uint32_t v) {
    return __uint_as_float(v & 0xffff0000u);
}
#define LDSM_X4(r0, r1, r2, r3, addr)                                        \
    asm volatile("ldmatrix.sync.aligned.m8n8.x4.shared.b16 {%0,%1,%2,%3}, [%4];" \
                 : "=r"(r0), "=r"(r1), "=r"(r2), "=r"(r3) : "r"(addr))

__device__ __forceinline__ void mma_bf16(float* c, const uint32_t* a,
                                         uint32_t b0, uint32_t b1) {
    asm volatile(
        "mma.sync.aligned.m16n8k16.row.col.f32.bf16.bf16.f32 "
        "{%0,%1,%2,%3}, {%4,%5,%6,%7}, {%8,%9}, {%0,%1,%2,%3};"
        : "+f"(c[0]), "+f"(c[1]), "+f"(c[2]), "+f"(c[3])
        : "r"(a[0]), "r"(a[1]), "r"(a[2]), "r"(a[3]), "r"(b0), "r"(b1));
}

// convert float4 -> (2 hi bf16x2 words, 2 lo bf16x2 words)
__device__ __forceinline__ void cvt_hilo(float4 v, uint32_t* hw, uint32_t* lw) {
    hw[0] = bf2(v.y, v.x);
    hw[1] = bf2(v.w, v.z);
    float r0 = v.x - bf_lo(hw[0]);
    float r1 = v.y - bf_hi(hw[0]);
    float r2 = v.z - bf_lo(hw[1]);
    float r3 = v.w - bf_hi(hw[1]);
    lw[0] = bf2(r1, r0);
    lw[1] = bf2(r3, r2);
}

// ---------------------------------------------------------------------------
// Per 128-edge tile (one CTA, 4 warps):
//   gather (4 lanes/edge): pos diff -> s_d; x -> A tile (bf16 hi/lo, 48B rows)
//   softmax (thread=edge): alpha*ea/sum -> s_al
//   GEMM: Y = X * Wt via mma.sync m16n8k16 bf16, 3-term emulation
//   alpha-combine in fragments, red.global.add.v2 scatter
// ---------------------------------------------------------------------------
__global__ __launch_bounds__(TPB, 4)
void genconv_mma_kernel(const float* __restrict__ x,
                        const float* __restrict__ pos,
                        const int*   __restrict__ ei,
                        const float* __restrict__ ea,
                        const float* __restrict__ offset,
                        const float* __restrict__ weight,
                        float* __restrict__ out, int E, int nTiles) {
    __shared__ __align__(16) unsigned char sAhi[TILE_E * ASTRIDE];
    __shared__ __align__(16) unsigned char sAlo[TILE_E * ASTRIDE];
    __shared__ __align__(16) unsigned char sBhi[128 * ASTRIDE];
    __shared__ __align__(16) unsigned char sBlo[128 * ASTRIDE];
    __shared__ __align__(16) float s_d[TILE_E * DSTRIDE];
    __shared__ __align__(16) float s_al[TILE_E * KOFF];
    __shared__ int   s_r[TILE_E];
    __shared__ float s_off[KOFF * POS_C];
    __shared__ float s_o2[KOFF];

    const int tid  = threadIdx.x;
    const int lane = tid & 31;
    const int wrp  = tid >> 5;

    const uint32_t uAhi = smem_u32(sAhi);
    const uint32_t uAlo = smem_u32(sAlo);
    const uint32_t uBhi = smem_u32(sBhi);
    const uint32_t uBlo = smem_u32(sBlo);

    // ---- stage offsets ----
    for (int i = tid; i < KOFF * POS_C; i += TPB) s_off[i] = offset[i];
    __syncthreads();
    if (tid < KOFF) {
        float s = 0.f;
#pragma unroll
        for (int p = 0; p < POS_C; p++) {
            float v = s_off[tid * POS_C + p];
            s += v * v;
        }
        s_o2[tid] = s;
    }

    // ---- build B tile once: row n = k*16+o = tid holds Wt[n][i] = W[k][o][i] ----
    {
        int k = tid >> 4, o = tid & 15;
        const float* wrow = weight + k * (OUT_C * IN_C) + o * IN_C;
#pragma unroll
        for (int q = 0; q < 4; q++) {
            float4 v = *reinterpret_cast<const float4*>(wrow + q * 4);
            uint32_t hw[2], lw[2];
            cvt_hilo(v, hw, lw);
            *reinterpret_cast<uint2*>(sBhi + tid * ASTRIDE + q * 8) =
                make_uint2(hw[0], hw[1]);
            *reinterpret_cast<uint2*>(sBlo + tid * ASTRIDE + q * 8) =
                make_uint2(lw[0], lw[1]);
        }
    }
    __syncthreads();

    for (int t = blockIdx.x; t < nTiles; t += gridDim.x) {
        // ============ gather: 4 lanes/edge, 4 passes ============
        const int ebg = tid >> 2;
        const int q   = tid & 3;
#pragma unroll
        for (int p = 0; p < 4; p++) {
            int el = p * 32 + ebg;
            int e  = min(t * TILE_E + el, E - 1);
            int r  = ei[e];
            int c  = ei[E + e];
            float4 av = *reinterpret_cast<const float4*>(pos + (size_t)c * POS_C + q * 4);
            float4 bv = *reinterpret_cast<const float4*>(pos + (size_t)r * POS_C + q * 4);
            float4 dq;
            dq.x = av.x - bv.x; dq.y = av.y - bv.y;
            dq.z = av.z - bv.z; dq.w = av.w - bv.w;
            *reinterpret_cast<float4*>(s_d + el * DSTRIDE + q * 4) = dq;

            float4 xv = *reinterpret_cast<const float4*>(x + (size_t)c * IN_C + q * 4);
            uint32_t hw[2], lw[2];
            cvt_hilo(xv, hw, lw);
            *reinterpret_cast<uint2*>(sAhi + el * ASTRIDE + q * 8) =
                make_uint2(hw[0], hw[1]);
            *reinterpret_cast<uint2*>(sAlo + el * ASTRIDE + q * 8) =
                make_uint2(lw[0], lw[1]);
            if (q == 0) s_r[el] = r;
        }
        __syncthreads();

        // ============ softmax: thread = edge ============
        {
            int et = t * TILE_E + tid;
            int valid = (et < E);
            int e = min(et, E - 1);

            float d[POS_C];
#pragma unroll
            for (int j = 0; j < 4; j++) {
                float4 v = *reinterpret_cast<const float4*>(s_d + tid * DSTRIDE + j * 4);
                d[4*j+0] = v.x; d[4*j+1] = v.y; d[4*j+2] = v.z; d[4*j+3] = v.w;
            }
            float d2 = 0.f;
#pragma unroll
            for (int p = 0; p < POS_C; p++) d2 += d[p] * d[p];

            float logit[KOFF];
            float mx = -1e30f;
#pragma unroll
            for (int k = 0; k < KOFF; k++) {
                float dot = 0.f;
                const float4* ok4 = reinterpret_cast<const float4*>(s_off + k * POS_C);
#pragma unroll
                for (int j = 0; j < 4; j++) {
                    float4 ov = ok4[j];
                    dot += d[4*j+0]*ov.x + d[4*j+1]*ov.y
                         + d[4*j+2]*ov.z + d[4*j+3]*ov.w;
                }
                float sq = fmaxf(d2 + s_o2[k] - 2.0f * dot, 0.0f);
                float l = -TEMP * sqrtf(sq);
                logit[k] = l;
                mx = fmaxf(mx, l);
            }
            float a[KOFF];
            float asum = 0.f;
#pragma unroll
            for (int k = 0; k < KOFF; k++) {
                float v = __expf(logit[k] - mx);
                a[k] = v;
                asum += v;
            }
            float inv = valid ? (ea[e] / asum) : 0.0f;
            float4* a4 = reinterpret_cast<float4*>(s_al + tid * KOFF);
            a4[0] = make_float4(a[0]*inv, a[1]*inv, a[2]*inv, a[3]*inv);
            a4[1] = make_float4(a[4]*inv, a[5]*inv, a[6]*inv, a[7]*inv);
        }
        __syncwarp();

        // ============ GEMM + alpha-combine ============
        // A fragments for this warp's 2 m-tiles (rows 32w .. 32w+31)
        uint32_t Ah[2][4], Al[2][4];
#pragma unroll
        for (int mt = 0; mt < 2; mt++) {
            uint32_t arow = (uint32_t)(wrp * 32 + mt * 16 + (lane & 15));
            uint32_t aoff = arow * ASTRIDE + (uint32_t)(lane >> 4) * 16;
            LDSM_X4(Ah[mt][0], Ah[mt][1], Ah[mt][2], Ah[mt][3], uAhi + aoff);
            LDSM_X4(Al[mt][0], Al[mt][1], Al[mt][2], Al[mt][3], uAlo + aoff);
        }

        float msg[2][2][2][2];   // [mt][rowhalf][ohalf][col]
#pragma unroll
        for (int i = 0; i < 2; i++)
#pragma unroll
            for (int j = 0; j < 2; j++)
#pragma unroll
                for (int kk = 0; kk < 2; kk++) {
                    msg[i][j][kk][0] = 0.f;
                    msg[i][j][kk][1] = 0.f;
                }

#pragma unroll
        for (int np = 0; np < 8; np++) {    // k = np; covers n-tiles 2np, 2np+1
            uint32_t boff = (uint32_t)(np * 16 + (lane & 15)) * ASTRIDE
                          + (uint32_t)(lane >> 4) * 16;
            uint32_t bh[4], bl[4];
            LDSM_X4(bh[0], bh[1], bh[2], bh[3], uBhi + boff);
            LDSM_X4(bl[0], bl[1], bl[2], bl[3], uBlo + boff);

            float aA[2][2];
#pragma unroll
            for (int mt = 0; mt < 2; mt++) {
                int er = wrp * 32 + mt * 16 + (lane >> 2);
                aA[mt][0] = s_al[er * KOFF + np];
                aA[mt][1] = s_al[(er + 8) * KOFF + np];
            }

#pragma unroll
            for (int mt = 0; mt < 2; mt++) {
                {   // sub-n 0 (ohalf 0): B frags {bh[0], bh[2]}
                    float c[4] = {0.f, 0.f, 0.f, 0.f};
                    mma_bf16(c, Ah[mt], bh[0], bh[2]);
                    mma_bf16(c, Ah[mt], bl[0], bl[2]);
                    mma_bf16(c, Al[mt], bh[0], bh[2]);
                    msg[mt][0][0][0] = fmaf(aA[mt][0], c[0], msg[mt][0][0][0]);
                    msg[mt][0][0][1] = fmaf(aA[mt][0], c[1], msg[mt][0][0][1]);
                    msg[mt][1][0][0] = fmaf(aA[mt][1], c[2], msg[mt][1][0][0]);
                    msg[mt][1][0][1] = fmaf(aA[mt][1], c[3], msg[mt][1][0][1]);
                }
                {   // sub-n 1 (ohalf 1): B frags {bh[1], bh[3]}
                    float c[4] = {0.f, 0.f, 0.f, 0.f};
                    mma_bf16(c, Ah[mt], bh[1], bh[3]);
                    mma_bf16(c, Ah[mt], bl[1], bl[3]);
                    mma_bf16(c, Al[mt], bh[1], bh[3]);
                    msg[mt][0][1][0] = fmaf(aA[mt][0], c[0], msg[mt][0][1][0]);
                    msg[mt][0][1][1] = fmaf(aA[mt][0], c[1], msg[mt][0][1][1]);
                    msg[mt][1][1][0] = fmaf(aA[mt][1], c[2], msg[mt][1][1][0]);
                    msg[mt][1][1][1] = fmaf(aA[mt][1], c[3], msg[mt][1][1][1]);
                }
            }
        }

        // ============ scatter: red.v2 per (mt, rowhalf, ohalf) ============
#pragma unroll
        for (int mt = 0; mt < 2; mt++) {
#pragma unroll
            for (int rh = 0; rh < 2; rh++) {
                int el = wrp * 32 + mt * 16 + rh * 8 + (lane >> 2);
                int rr = s_r[el];
                float* dst = out + (size_t)rr * OUT_C + 2 * (lane & 3);
                asm volatile("red.global.add.v2.f32 [%0], {%1, %2};"
                             :: "l"(dst), "f"(msg[mt][rh][0][0]),
                                "f"(msg[mt][rh][0][1]) : "memory");
                asm volatile("red.global.add.v2.f32 [%0], {%1, %2};"
                             :: "l"(dst + 8), "f"(msg[mt][rh][1][0]),
                                "f"(msg[mt][rh][1][1]) : "memory");
            }
        }
        __syncthreads();   // protect A/s_d before next tile's gather
    }
}

// ---------------------------------------------------------------------------
extern "C" void kernel_launch(void* const* d_in, const int* in_sizes, int n_in,
                              void* d_out, int out_size) {
    const float* x      = (const float*)d_in[0];
    const float* pos    = (const float*)d_in[1];
    const int*   ei     = (const int*)  d_in[2];
    const float* ea     = (const float*)d_in[3];
    const float* offset = (const float*)d_in[4];
    const float* weight = (const float*)d_in[5];
    const float* bias   = (const float*)d_in[6];
    float* out = (float*)d_out;

    int E = in_sizes[3];
    int total_out = out_size;

    int init_blocks = (total_out + 255) / 256;
    init_out_kernel<<<init_blocks, 256>>>(out, bias, total_out);

    int nTiles = (E + TILE_E - 1) / TILE_E;
    int blocks = 592;                       // 4 per SM, persistent
    if (blocks > nTiles) blocks = nTiles;
    genconv_mma_kernel<<<blocks, TPB>>>(x, pos, ei, ea, offset, weight,
                                        out, E, nTiles);
}

// round 10
// speedup vs baseline: 2.0981x; 1.1205x over previous
#include <cuda_runtime.h>
#include <cstdint>

#define IN_C     16
#define OUT_C    16
#define POS_C    16
#define KOFF     8
#define TEMP     8.0f
#define TPB      128
#define TILE_E   128
#define DSTRIDE  20
#define ASTRIDE  48            // bytes per A/B smem row (16 bf16 data + pad)

// ---------------------------------------------------------------------------
__global__ void init_out_kernel(float* __restrict__ out,
                                const float* __restrict__ bias, int total) {
    int idx = blockIdx.x * blockDim.x + threadIdx.x;
    if (idx < total) out[idx] = bias[idx & (OUT_C - 1)];
}

// ---------------------------------------------------------------------------
__device__ __forceinline__ uint32_t smem_u32(const void* p) {
    uint32_t a;
    asm("{ .reg .u64 t; cvta.to.shared.u64 t, %1; cvt.u32.u64 %0, t; }"
        : "=r"(a) : "l"(p));
    return a;
}
__device__ __forceinline__ uint32_t bf2(float h, float l) {
    uint32_t r;
    asm("cvt.rn.bf16x2.f32 %0, %1, %2;" : "=r"(r) : "f"(h), "f"(l));
    return r;
}
__device__ __forceinline__ float bf_lo(uint32_t v) { return __uint_as_float(v << 16); }
__device__ __forceinline__ float bf_hi(uint32_t v) { return __uint_as_float(v & 0xffff0000u); }

#define LDSM_X4(r0, r1, r2, r3, addr)                                        \
    asm volatile("ldmatrix.sync.aligned.m8n8.x4.shared.b16 {%0,%1,%2,%3}, [%4];" \
                 : "=r"(r0), "=r"(r1), "=r"(r2), "=r"(r3) : "r"(addr))

__device__ __forceinline__ void mma_bf16(float* c, const uint32_t* a,
                                         uint32_t b0, uint32_t b1) {
    asm volatile(
        "mma.sync.aligned.m16n8k16.row.col.f32.bf16.bf16.f32 "
        "{%0,%1,%2,%3}, {%4,%5,%6,%7}, {%8,%9}, {%0,%1,%2,%3};"
        : "+f"(c[0]), "+f"(c[1]), "+f"(c[2]), "+f"(c[3])
        : "r"(a[0]), "r"(a[1]), "r"(a[2]), "r"(a[3]), "r"(b0), "r"(b1));
}

__device__ __forceinline__ void cvt_hilo(float4 v, uint32_t* hw, uint32_t* lw) {
    hw[0] = bf2(v.y, v.x);
    hw[1] = bf2(v.w, v.z);
    float r0 = v.x - bf_lo(hw[0]);
    float r1 = v.y - bf_hi(hw[0]);
    float r2 = v.z - bf_lo(hw[1]);
    float r3 = v.w - bf_hi(hw[1]);
    lw[0] = bf2(r1, r0);
    lw[1] = bf2(r3, r2);
}

// ---------------------------------------------------------------------------
// Per 128-edge tile (one CTA, 4 warps):
//   gather (4 lanes/edge): pos diff -> s_d; x -> A tile (bf16 hi/lo, 48B rows)
//   softmax (thread=edge): alpha*ea/sum -> s_al
//   GEMM: Y = X * Wt via mma.sync m16n8k16 bf16, 3-term emulation.
//   B (weight) fragments are loaded ONCE into registers before the tile loop
//   (tile-invariant): removes 16 LDSM.x4 per warp-tile from the L1 pipe.
//   alpha-combine in fragments, red.global.add.v2 scatter.
// ---------------------------------------------------------------------------
__global__ __launch_bounds__(TPB, 4)
void genconv_mma_kernel(const float* __restrict__ x,
                        const float* __restrict__ pos,
                        const int*   __restrict__ ei,
                        const float* __restrict__ ea,
                        const float* __restrict__ offset,
                        const float* __restrict__ weight,
                        float* __restrict__ out, int E, int nTiles) {
    __shared__ __align__(16) unsigned char sAhi[TILE_E * ASTRIDE];
    __shared__ __align__(16) unsigned char sAlo[TILE_E * ASTRIDE];
    __shared__ __align__(16) unsigned char sBhi[128 * ASTRIDE];
    __shared__ __align__(16) unsigned char sBlo[128 * ASTRIDE];
    __shared__ __align__(16) float s_d[TILE_E * DSTRIDE];
    __shared__ __align__(16) float s_al[TILE_E * KOFF];
    __shared__ int   s_r[TILE_E];
    __shared__ float s_off[KOFF * POS_C];
    __shared__ float s_o2[KOFF];

    const int tid  = threadIdx.x;
    const int lane = tid & 31;
    const int wrp  = tid >> 5;

    const uint32_t uAhi = smem_u32(sAhi);
    const uint32_t uAlo = smem_u32(sAlo);
    const uint32_t uBhi = smem_u32(sBhi);
    const uint32_t uBlo = smem_u32(sBlo);

    // ---- stage offsets ----
    for (int i = tid; i < KOFF * POS_C; i += TPB) s_off[i] = offset[i];
    __syncthreads();
    if (tid < KOFF) {
        float s = 0.f;
#pragma unroll
        for (int p = 0; p < POS_C; p++) {
            float v = s_off[tid * POS_C + p];
            s += v * v;
        }
        s_o2[tid] = s;
    }

    // ---- build B tile once: row n = k*16+o = tid holds Wt[n][i] = W[k][o][i] ----
    {
        int k = tid >> 4, o = tid & 15;
        const float* wrow = weight + k * (OUT_C * IN_C) + o * IN_C;
#pragma unroll
        for (int q = 0; q < 4; q++) {
            float4 v = *reinterpret_cast<const float4*>(wrow + q * 4);
            uint32_t hw[2], lw[2];
            cvt_hilo(v, hw, lw);
            *reinterpret_cast<uint2*>(sBhi + tid * ASTRIDE + q * 8) =
                make_uint2(hw[0], hw[1]);
            *reinterpret_cast<uint2*>(sBlo + tid * ASTRIDE + q * 8) =
                make_uint2(lw[0], lw[1]);
        }
    }
    __syncthreads();

    // ---- persistent B fragments: loaded once, live across all tiles ----
    uint32_t Bh[8][4], Bl[8][4];
#pragma unroll
    for (int np = 0; np < 8; np++) {
        uint32_t boff = (uint32_t)(np * 16 + (lane & 15)) * ASTRIDE
                      + (uint32_t)(lane >> 4) * 16;
        LDSM_X4(Bh[np][0], Bh[np][1], Bh[np][2], Bh[np][3], uBhi + boff);
        LDSM_X4(Bl[np][0], Bl[np][1], Bl[np][2], Bl[np][3], uBlo + boff);
    }

    for (int t = blockIdx.x; t < nTiles; t += gridDim.x) {
        // ============ gather: 4 lanes/edge, 4 passes ============
        const int ebg = tid >> 2;
        const int q   = tid & 3;
#pragma unroll
        for (int p = 0; p < 4; p++) {
            int el = p * 32 + ebg;
            int e  = min(t * TILE_E + el, E - 1);
            int r  = ei[e];
            int c  = ei[E + e];
            float4 av = *reinterpret_cast<const float4*>(pos + (size_t)c * POS_C + q * 4);
            float4 bv = *reinterpret_cast<const float4*>(pos + (size_t)r * POS_C + q * 4);
            float4 dq;
            dq.x = av.x - bv.x; dq.y = av.y - bv.y;
            dq.z = av.z - bv.z; dq.w = av.w - bv.w;
            *reinterpret_cast<float4*>(s_d + el * DSTRIDE + q * 4) = dq;

            float4 xv = *reinterpret_cast<const float4*>(x + (size_t)c * IN_C + q * 4);
            uint32_t hw[2], lw[2];
            cvt_hilo(xv, hw, lw);
            *reinterpret_cast<uint2*>(sAhi + el * ASTRIDE + q * 8) =
                make_uint2(hw[0], hw[1]);
            *reinterpret_cast<uint2*>(sAlo + el * ASTRIDE + q * 8) =
                make_uint2(lw[0], lw[1]);
            if (q == 0) s_r[el] = r;
        }
        __syncthreads();

        // ============ softmax: thread = edge ============
        {
            int et = t * TILE_E + tid;
            int valid = (et < E);
            int e = min(et, E - 1);

            float d[POS_C];
#pragma unroll
            for (int j = 0; j < 4; j++) {
                float4 v = *reinterpret_cast<const float4*>(s_d + tid * DSTRIDE + j * 4);
                d[4*j+0] = v.x; d[4*j+1] = v.y; d[4*j+2] = v.z; d[4*j+3] = v.w;
            }
            float d2 = 0.f;
#pragma unroll
            for (int p = 0; p < POS_C; p++) d2 += d[p] * d[p];

            float logit[KOFF];
            float mx = -1e30f;
#pragma unroll
            for (int k = 0; k < KOFF; k++) {
                float dot = 0.f;
                const float4* ok4 = reinterpret_cast<const float4*>(s_off + k * POS_C);
#pragma unroll
                for (int j = 0; j < 4; j++) {
                    float4 ov = ok4[j];
                    dot += d[4*j+0]*ov.x + d[4*j+1]*ov.y
                         + d[4*j+2]*ov.z + d[4*j+3]*ov.w;
                }
                float sq = fmaxf(d2 + s_o2[k] - 2.0f * dot, 0.0f);
                float l = -TEMP * sqrtf(sq);
                logit[k] = l;
                mx = fmaxf(mx, l);
            }
            float a[KOFF];
            float asum = 0.f;
#pragma unroll
            for (int k = 0; k < KOFF; k++) {
                float v = __expf(logit[k] - mx);
                a[k] = v;
                asum += v;
            }
            float inv = valid ? (ea[e] / asum) : 0.0f;
            float4* a4 = reinterpret_cast<float4*>(s_al + tid * KOFF);
            a4[0] = make_float4(a[0]*inv, a[1]*inv, a[2]*inv, a[3]*inv);
            a4[1] = make_float4(a[4]*inv, a[5]*inv, a[6]*inv, a[7]*inv);
        }
        __syncwarp();

        // ============ GEMM + alpha-combine ============
        uint32_t Ah[2][4], Al[2][4];
#pragma unroll
        for (int mt = 0; mt < 2; mt++) {
            uint32_t arow = (uint32_t)(wrp * 32 + mt * 16 + (lane & 15));
            uint32_t aoff = arow * ASTRIDE + (uint32_t)(lane >> 4) * 16;
            LDSM_X4(Ah[mt][0], Ah[mt][1], Ah[mt][2], Ah[mt][3], uAhi + aoff);
            LDSM_X4(Al[mt][0], Al[mt][1], Al[mt][2], Al[mt][3], uAlo + aoff);
        }

        float msg[2][2][2][2];   // [mt][rowhalf][ohalf][col]
#pragma unroll
        for (int i = 0; i < 2; i++)
#pragma unroll
            for (int j = 0; j < 2; j++)
#pragma unroll
                for (int kk = 0; kk < 2; kk++) {
                    msg[i][j][kk][0] = 0.f;
                    msg[i][j][kk][1] = 0.f;
                }

#pragma unroll
        for (int np = 0; np < 8; np++) {    // k = np; n-tiles 2np, 2np+1
            float aA[2][2];
#pragma unroll
            for (int mt = 0; mt < 2; mt++) {
                int er = wrp * 32 + mt * 16 + (lane >> 2);
                aA[mt][0] = s_al[er * KOFF + np];
                aA[mt][1] = s_al[(er + 8) * KOFF + np];
            }

#pragma unroll
            for (int mt = 0; mt < 2; mt++) {
                {   // sub-n 0 (ohalf 0): B frags {b[0], b[2]}
                    float c[4] = {0.f, 0.f, 0.f, 0.f};
                    mma_bf16(c, Ah[mt], Bh[np][0], Bh[np][2]);
                    mma_bf16(c, Ah[mt], Bl[np][0], Bl[np][2]);
                    mma_bf16(c, Al[mt], Bh[np][0], Bh[np][2]);
                    msg[mt][0][0][0] = fmaf(aA[mt][0], c[0], msg[mt][0][0][0]);
                    msg[mt][0][0][1] = fmaf(aA[mt][0], c[1], msg[mt][0][0][1]);
                    msg[mt][1][0][0] = fmaf(aA[mt][1], c[2], msg[mt][1][0][0]);
                    msg[mt][1][0][1] = fmaf(aA[mt][1], c[3], msg[mt][1][0][1]);
                }
                {   // sub-n 1 (ohalf 1): B frags {b[1], b[3]}
                    float c[4] = {0.f, 0.f, 0.f, 0.f};
                    mma_bf16(c, Ah[mt], Bh[np][1], Bh[np][3]);
                    mma_bf16(c, Ah[mt], Bl[np][1], Bl[np][3]);
                    mma_bf16(c, Al[mt], Bh[np][1], Bh[np][3]);
                    msg[mt][0][1][0] = fmaf(aA[mt][0], c[0], msg[mt][0][1][0]);
                    msg[mt][0][1][1] = fmaf(aA[mt][0], c[1], msg[mt][0][1][1]);
                    msg[mt][1][1][0] = fmaf(aA[mt][1], c[2], msg[mt][1][1][0]);
                    msg[mt][1][1][1] = fmaf(aA[mt][1], c[3], msg[mt][1][1][1]);
                }
            }
        }

        // ============ scatter: red.v2 per (mt, rowhalf, ohalf) ============
#pragma unroll
        for (int mt = 0; mt < 2; mt++) {
#pragma unroll
            for (int rh = 0; rh < 2; rh++) {
                int el = wrp * 32 + mt * 16 + rh * 8 + (lane >> 2);
                int rr = s_r[el];
                float* dst = out + (size_t)rr * OUT_C + 2 * (lane & 3);
                asm volatile("red.global.add.v2.f32 [%0], {%1, %2};"
                             :: "l"(dst), "f"(msg[mt][rh][0][0]),
                                "f"(msg[mt][rh][0][1]) : "memory");
                asm volatile("red.global.add.v2.f32 [%0], {%1, %2};"
                             :: "l"(dst + 8), "f"(msg[mt][rh][1][0]),
                                "f"(msg[mt][rh][1][1]) : "memory");
            }
        }
        __syncthreads();   // protect A/s_d before next tile's gather
    }
}

// ---------------------------------------------------------------------------
extern "C" void kernel_launch(void* const* d_in, const int* in_sizes, int n_in,
                              void* d_out, int out_size) {
    const float* x      = (const float*)d_in[0];
    const float* pos    = (const float*)d_in[1];
    const int*   ei     = (const int*)  d_in[2];
    const float* ea     = (const float*)d_in[3];
    const float* offset = (const float*)d_in[4];
    const float* weight = (const float*)d_in[5];
    const float* bias   = (const float*)d_in[6];
    float* out = (float*)d_out;

    int E = in_sizes[3];
    int total_out = out_size;

    int init_blocks = (total_out + 255) / 256;
    init_out_kernel<<<init_blocks, 256>>>(out, bias, total_out);

    int nTiles = (E + TILE_E - 1) / TILE_E;
    int blocks = 592;                       // 4 per SM, persistent
    if (blocks > nTiles) blocks = nTiles;
    genconv_mma_kernel<<<blocks, TPB>>>(x, pos, ei, ea, offset, weight,
                                        out, E, nTiles);
}

// round 11
// speedup vs baseline: 2.1953x; 1.0463x over previous
#include <cuda_runtime.h>
#include <cstdint>

#define IN_C     16
#define OUT_C    16
#define POS_C    16
#define KOFF     8
#define TEMP     8.0f
#define TPB      128
#define TILE_E   128
#define ASTRIDE  48            // bytes per bf16 tile row (16 bf16 + pad)
#define ALSTRIDE 12            // floats per edge row in s_al (16B-aligned, conflict-free)

// ---------------------------------------------------------------------------
__global__ void init_out_kernel(float* __restrict__ out,
                                const float* __restrict__ bias, int total) {
    int idx = blockIdx.x * blockDim.x + threadIdx.x;
    if (idx < total) out[idx] = bias[idx & (OUT_C - 1)];
}

// ---------------------------------------------------------------------------
__device__ __forceinline__ uint32_t smem_u32(const void* p) {
    uint32_t a;
    asm("{ .reg .u64 t; cvta.to.shared.u64 t, %1; cvt.u32.u64 %0, t; }"
        : "=r"(a) : "l"(p));
    return a;
}
__device__ __forceinline__ uint32_t bf2(float h, float l) {
    uint32_t r;
    asm("cvt.rn.bf16x2.f32 %0, %1, %2;" : "=r"(r) : "f"(h), "f"(l));
    return r;
}
__device__ __forceinline__ float bf_lo(uint32_t v) { return __uint_as_float(v << 16); }
__device__ __forceinline__ float bf_hi(uint32_t v) { return __uint_as_float(v & 0xffff0000u); }
__device__ __forceinline__ float rcpf(float v) {
    float r;
    asm("rcp.approx.f32 %0, %1;" : "=f"(r) : "f"(v));
    return r;
}

#define LDSM_X4(r0, r1, r2, r3, addr)                                        \
    asm volatile("ldmatrix.sync.aligned.m8n8.x4.shared.b16 {%0,%1,%2,%3}, [%4];" \
                 : "=r"(r0), "=r"(r1), "=r"(r2), "=r"(r3) : "r"(addr))
#define LDSM_X2(r0, r1, addr)                                                \
    asm volatile("ldmatrix.sync.aligned.m8n8.x2.shared.b16 {%0,%1}, [%2];"   \
                 : "=r"(r0), "=r"(r1) : "r"(addr))

__device__ __forceinline__ void mma_bf16(float* c, const uint32_t* a,
                                         uint32_t b0, uint32_t b1) {
    asm volatile(
        "mma.sync.aligned.m16n8k16.row.col.f32.bf16.bf16.f32 "
        "{%0,%1,%2,%3}, {%4,%5,%6,%7}, {%8,%9}, {%0,%1,%2,%3};"
        : "+f"(c[0]), "+f"(c[1]), "+f"(c[2]), "+f"(c[3])
        : "r"(a[0]), "r"(a[1]), "r"(a[2]), "r"(a[3]), "r"(b0), "r"(b1));
}

__device__ __forceinline__ void cvt_hilo(float4 v, uint32_t* hw, uint32_t* lw) {
    hw[0] = bf2(v.y, v.x);
    hw[1] = bf2(v.w, v.z);
    float r0 = v.x - bf_lo(hw[0]);
    float r1 = v.y - bf_hi(hw[0]);
    float r2 = v.z - bf_lo(hw[1]);
    float r3 = v.w - bf_hi(hw[1]);
    lw[0] = bf2(r1, r0);
    lw[1] = bf2(r3, r2);
}

// ---------------------------------------------------------------------------
// Per 128-edge tile (4 warps):
//  gather (4 lanes/edge): d = pos diff -> bf16 hi/lo D tile + d2 (shfl-reduced),
//    x -> bf16 hi/lo A tile, r/ea -> SMEM.
//  logit GEMM: [32e x16] d * [16 x 8] (-2*offset) via 6 mma.sync (3-term bf16);
//    softmax entirely in fragment layout (shfl row-max/row-sum), alpha -> s_al.
//  Y-GEMM per mt: persistent B regs, 48 mma.sync, alpha from 4 LDS.128,
//    red.global.add.v2 scatter.
// ---------------------------------------------------------------------------
__global__ __launch_bounds__(TPB, 4)
void genconv_mma_kernel(const float* __restrict__ x,
                        const float* __restrict__ pos,
                        const int*   __restrict__ ei,
                        const float* __restrict__ ea,
                        const float* __restrict__ offset,
                        const float* __restrict__ weight,
                        float* __restrict__ out, int E, int nTiles) {
    __shared__ __align__(16) unsigned char sAhi[TILE_E * ASTRIDE];
    __shared__ __align__(16) unsigned char sAlo[TILE_E * ASTRIDE];
    __shared__ __align__(16) unsigned char sBhi[128 * ASTRIDE];
    __shared__ __align__(16) unsigned char sBlo[128 * ASTRIDE];
    __shared__ __align__(16) unsigned char sDhi[TILE_E * ASTRIDE];
    __shared__ __align__(16) unsigned char sDlo[TILE_E * ASTRIDE];
    __shared__ __align__(16) unsigned char sOfh[8 * ASTRIDE];
    __shared__ __align__(16) unsigned char sOfl[8 * ASTRIDE];
    __shared__ __align__(16) float s_al[TILE_E * ALSTRIDE];
    __shared__ __align__(16) float s_d2[TILE_E];
    __shared__ __align__(16) float s_ea[TILE_E];
    __shared__ __align__(16) int   s_r[TILE_E];
    __shared__ __align__(16) float s_o2[KOFF];

    const int tid  = threadIdx.x;
    const int lane = tid & 31;
    const int wrp  = tid >> 5;

    const uint32_t uAhi = smem_u32(sAhi);
    const uint32_t uAlo = smem_u32(sAlo);
    const uint32_t uBhi = smem_u32(sBhi);
    const uint32_t uBlo = smem_u32(sBlo);
    const uint32_t uDhi = smem_u32(sDhi);
    const uint32_t uDlo = smem_u32(sDlo);
    const uint32_t uOfh = smem_u32(sOfh);
    const uint32_t uOfl = smem_u32(sOfl);

    // ---- init: o2 + (-2*offset) bf16 tile (rows n=0..7, 16 k-cols) ----
    if (tid < KOFF) {
        float s = 0.f;
        const float* orow = offset + tid * POS_C;
#pragma unroll
        for (int p = 0; p < POS_C; p++) s += orow[p] * orow[p];
        s_o2[tid] = s;
#pragma unroll
        for (int q = 0; q < 4; q++) {
            float4 v = *reinterpret_cast<const float4*>(orow + q * 4);
            v.x *= -2.f; v.y *= -2.f; v.z *= -2.f; v.w *= -2.f;
            uint32_t hw[2], lw[2];
            cvt_hilo(v, hw, lw);
            *reinterpret_cast<uint2*>(sOfh + tid * ASTRIDE + q * 8) = make_uint2(hw[0], hw[1]);
            *reinterpret_cast<uint2*>(sOfl + tid * ASTRIDE + q * 8) = make_uint2(lw[0], lw[1]);
        }
    }

    // ---- build B tile: row n = k*16+o = tid holds W[k][o][0:16] ----
    {
        int k = tid >> 4, o = tid & 15;
        const float* wrow = weight + k * (OUT_C * IN_C) + o * IN_C;
#pragma unroll
        for (int q = 0; q < 4; q++) {
            float4 v = *reinterpret_cast<const float4*>(wrow + q * 4);
            uint32_t hw[2], lw[2];
            cvt_hilo(v, hw, lw);
            *reinterpret_cast<uint2*>(sBhi + tid * ASTRIDE + q * 8) = make_uint2(hw[0], hw[1]);
            *reinterpret_cast<uint2*>(sBlo + tid * ASTRIDE + q * 8) = make_uint2(lw[0], lw[1]);
        }
    }
    __syncthreads();

    // ---- persistent fragments: B (weights) and O (offsets) ----
    uint32_t Bh[8][4], Bl[8][4];
#pragma unroll
    for (int np = 0; np < 8; np++) {
        uint32_t boff = (uint32_t)(np * 16 + (lane & 15)) * ASTRIDE
                      + (uint32_t)(lane >> 4) * 16;
        LDSM_X4(Bh[np][0], Bh[np][1], Bh[np][2], Bh[np][3], uBhi + boff);
        LDSM_X4(Bl[np][0], Bl[np][1], Bl[np][2], Bl[np][3], uBlo + boff);
    }
    uint32_t Oh[2], Ol[2];
    {
        uint32_t ooff = (uint32_t)(lane & 7) * ASTRIDE + ((uint32_t)(lane >> 3) & 1) * 16;
        LDSM_X2(Oh[0], Oh[1], uOfh + ooff);
        LDSM_X2(Ol[0], Ol[1], uOfl + ooff);
    }

    for (int t = blockIdx.x; t < nTiles; t += gridDim.x) {
        // ============ gather: 4 lanes/edge, 4 passes ============
        const int ebg = tid >> 2;
        const int q   = tid & 3;
#pragma unroll
        for (int p = 0; p < 4; p++) {
            int el = p * 32 + ebg;
            int e  = min(t * TILE_E + el, E - 1);
            int r  = ei[e];
            int c  = ei[E + e];
            float4 av = *reinterpret_cast<const float4*>(pos + (size_t)c * POS_C + q * 4);
            float4 bv = *reinterpret_cast<const float4*>(pos + (size_t)r * POS_C + q * 4);
            float4 dq;
            dq.x = av.x - bv.x; dq.y = av.y - bv.y;
            dq.z = av.z - bv.z; dq.w = av.w - bv.w;

            float p2 = dq.x*dq.x + dq.y*dq.y + dq.z*dq.z + dq.w*dq.w;
            p2 += __shfl_xor_sync(0xffffffffu, p2, 1);
            p2 += __shfl_xor_sync(0xffffffffu, p2, 2);

            uint32_t hw[2], lw[2];
            cvt_hilo(dq, hw, lw);
            *reinterpret_cast<uint2*>(sDhi + el * ASTRIDE + q * 8) = make_uint2(hw[0], hw[1]);
            *reinterpret_cast<uint2*>(sDlo + el * ASTRIDE + q * 8) = make_uint2(lw[0], lw[1]);

            float4 xv = *reinterpret_cast<const float4*>(x + (size_t)c * IN_C + q * 4);
            cvt_hilo(xv, hw, lw);
            *reinterpret_cast<uint2*>(sAhi + el * ASTRIDE + q * 8) = make_uint2(hw[0], hw[1]);
            *reinterpret_cast<uint2*>(sAlo + el * ASTRIDE + q * 8) = make_uint2(lw[0], lw[1]);

            if (q == 0) {
                s_r[el]  = r;
                s_d2[el] = p2;
                s_ea[el] = ea[e];
            }
        }
        __syncthreads();

        // ============ logit GEMM: d[32x16] * (-2*off)^T[16x8] ============
        float cl[2][4];
        {
#pragma unroll
            for (int mt = 0; mt < 2; mt++) {
                uint32_t Dh[4], Dl[4];
                uint32_t aoff = (uint32_t)(wrp * 32 + mt * 16 + (lane & 15)) * ASTRIDE
                              + (uint32_t)(lane >> 4) * 16;
                LDSM_X4(Dh[0], Dh[1], Dh[2], Dh[3], uDhi + aoff);
                LDSM_X4(Dl[0], Dl[1], Dl[2], Dl[3], uDlo + aoff);
                cl[mt][0] = cl[mt][1] = cl[mt][2] = cl[mt][3] = 0.f;
                mma_bf16(cl[mt], Dh, Oh[0], Oh[1]);
                mma_bf16(cl[mt], Dh, Ol[0], Ol[1]);
                mma_bf16(cl[mt], Dl, Oh[0], Oh[1]);
            }
        }

        // ============ softmax in fragment layout ============
        {
            const int rb  = wrp * 32 + (lane >> 2);
            const int np0 = 2 * (lane & 3);
            float2 o2p = *reinterpret_cast<const float2*>(&s_o2[np0]);

            float lg[2][2][2], mx[2][2];
#pragma unroll
            for (int mt = 0; mt < 2; mt++) {
                float d2a = s_d2[rb + mt * 16];
                float d2b = s_d2[rb + mt * 16 + 8];
                lg[mt][0][0] = -TEMP * sqrtf(fmaxf(d2a + o2p.x + cl[mt][0], 0.f));
                lg[mt][0][1] = -TEMP * sqrtf(fmaxf(d2a + o2p.y + cl[mt][1], 0.f));
                lg[mt][1][0] = -TEMP * sqrtf(fmaxf(d2b + o2p.x + cl[mt][2], 0.f));
                lg[mt][1][1] = -TEMP * sqrtf(fmaxf(d2b + o2p.y + cl[mt][3], 0.f));
                mx[mt][0] = fmaxf(lg[mt][0][0], lg[mt][0][1]);
                mx[mt][1] = fmaxf(lg[mt][1][0], lg[mt][1][1]);
            }
#pragma unroll
            for (int mt = 0; mt < 2; mt++)
#pragma unroll
                for (int rh = 0; rh < 2; rh++) {
                    float m = mx[mt][rh];
                    m = fmaxf(m, __shfl_xor_sync(0xffffffffu, m, 1));
                    m = fmaxf(m, __shfl_xor_sync(0xffffffffu, m, 2));
                    mx[mt][rh] = m;
                }
            float ev[2][2][2], sm[2][2];
#pragma unroll
            for (int mt = 0; mt < 2; mt++)
#pragma unroll
                for (int rh = 0; rh < 2; rh++) {
                    ev[mt][rh][0] = __expf(lg[mt][rh][0] - mx[mt][rh]);
                    ev[mt][rh][1] = __expf(lg[mt][rh][1] - mx[mt][rh]);
                    float s = ev[mt][rh][0] + ev[mt][rh][1];
                    s += __shfl_xor_sync(0xffffffffu, s, 1);
                    s += __shfl_xor_sync(0xffffffffu, s, 2);
                    sm[mt][rh] = s;
                }
#pragma unroll
            for (int mt = 0; mt < 2; mt++)
#pragma unroll
                for (int rh = 0; rh < 2; rh++) {
                    int el = rb + mt * 16 + rh * 8;
                    int valid = (t * TILE_E + el) < E;
                    float inv = valid ? (s_ea[el] * rcpf(sm[mt][rh])) : 0.f;
                    float2 al2;
                    al2.x = ev[mt][rh][0] * inv;
                    al2.y = ev[mt][rh][1] * inv;
                    *reinterpret_cast<float2*>(&s_al[el * ALSTRIDE + np0]) = al2;
                }
        }
        __syncwarp();

        // ============ Y-GEMM per mt + scatter ============
#pragma unroll
        for (int mt = 0; mt < 2; mt++) {
            float alr[2][8];
#pragma unroll
            for (int rh = 0; rh < 2; rh++) {
                int el = wrp * 32 + mt * 16 + rh * 8 + (lane >> 2);
                float4 a0 = *reinterpret_cast<const float4*>(&s_al[el * ALSTRIDE]);
                float4 a1 = *reinterpret_cast<const float4*>(&s_al[el * ALSTRIDE + 4]);
                alr[rh][0] = a0.x; alr[rh][1] = a0.y; alr[rh][2] = a0.z; alr[rh][3] = a0.w;
                alr[rh][4] = a1.x; alr[rh][5] = a1.y; alr[rh][6] = a1.z; alr[rh][7] = a1.w;
            }
            uint32_t Ah[4], Al[4];
            {
                uint32_t aoff = (uint32_t)(wrp * 32 + mt * 16 + (lane & 15)) * ASTRIDE
                              + (uint32_t)(lane >> 4) * 16;
                LDSM_X4(Ah[0], Ah[1], Ah[2], Ah[3], uAhi + aoff);
                LDSM_X4(Al[0], Al[1], Al[2], Al[3], uAlo + aoff);
            }
            float msg[2][2][2];   // [rowhalf][ohalf][col]
#pragma unroll
            for (int i = 0; i < 2; i++)
#pragma unroll
                for (int j = 0; j < 2; j++) { msg[i][j][0] = 0.f; msg[i][j][1] = 0.f; }

#pragma unroll
            for (int np = 0; np < 8; np++) {
                float aA0 = alr[0][np];
                float aA1 = alr[1][np];
                {
                    float c[4] = {0.f, 0.f, 0.f, 0.f};
                    mma_bf16(c, Ah, Bh[np][0], Bh[np][2]);
                    mma_bf16(c, Ah, Bl[np][0], Bl[np][2]);
                    mma_bf16(c, Al, Bh[np][0], Bh[np][2]);
                    msg[0][0][0] = fmaf(aA0, c[0], msg[0][0][0]);
                    msg[0][0][1] = fmaf(aA0, c[1], msg[0][0][1]);
                    msg[1][0][0] = fmaf(aA1, c[2], msg[1][0][0]);
                    msg[1][0][1] = fmaf(aA1, c[3], msg[1][0][1]);
                }
                {
                    float c[4] = {0.f, 0.f, 0.f, 0.f};
                    mma_bf16(c, Ah, Bh[np][1], Bh[np][3]);
                    mma_bf16(c, Ah, Bl[np][1], Bl[np][3]);
                    mma_bf16(c, Al, Bh[np][1], Bh[np][3]);
                    msg[0][1][0] = fmaf(aA0, c[0], msg[0][1][0]);
                    msg[0][1][1] = fmaf(aA0, c[1], msg[0][1][1]);
                    msg[1][1][0] = fmaf(aA1, c[2], msg[1][1][0]);
                    msg[1][1][1] = fmaf(aA1, c[3], msg[1][1][1]);
                }
            }
#pragma unroll
            for (int rh = 0; rh < 2; rh++) {
                int el = wrp * 32 + mt * 16 + rh * 8 + (lane >> 2);
                int rr = s_r[el];
                float* dst = out + (size_t)rr * OUT_C + 2 * (lane & 3);
                asm volatile("red.global.add.v2.f32 [%0], {%1, %2};"
                             :: "l"(dst), "f"(msg[rh][0][0]), "f"(msg[rh][0][1]) : "memory");
                asm volatile("red.global.add.v2.f32 [%0], {%1, %2};"
                             :: "l"(dst + 8), "f"(msg[rh][1][0]), "f"(msg[rh][1][1]) : "memory");
            }
        }
        __syncthreads();   // protect tiles before next gather
    }
}

// ---------------------------------------------------------------------------
extern "C" void kernel_launch(void* const* d_in, const int* in_sizes, int n_in,
                              void* d_out, int out_size) {
    const float* x      = (const float*)d_in[0];
    const float* pos    = (const float*)d_in[1];
    const int*   ei     = (const int*)  d_in[2];
    const float* ea     = (const float*)d_in[3];
    const float* offset = (const float*)d_in[4];
    const float* weight = (const float*)d_in[5];
    const float* bias   = (const float*)d_in[6];
    float* out = (float*)d_out;

    int E = in_sizes[3];
    int total_out = out_size;

    int init_blocks = (total_out + 255) / 256;
    init_out_kernel<<<init_blocks, 256>>>(out, bias, total_out);

    int nTiles = (E + TILE_E - 1) / TILE_E;
    int blocks = 592;                       // 4 per SM, persistent
    if (blocks > nTiles) blocks = nTiles;
    genconv_mma_kernel<<<blocks, TPB>>>(x, pos, ei, ea, offset, weight,
                                        out, E, nTiles);
}